// round 14
// baseline (speedup 1.0000x reference)
#include <cuda_runtime.h>
#include <cuda_fp16.h>
#include <cstdint>

#define EMBED 256
#define HEADS 4
#define HDIM  64
#define BATCH 4
#define SQL   512
#define SKL   512
#define MTOT  (BATCH*SQL)   /* 2048 */

// Scratch (allocation-free rule: __device__ globals)
__device__ __half g_Qh[MTOT*EMBED];   // Q projection, half
__device__ __half g_Kh[MTOT*EMBED];   // K projection, half
__device__ float  g_V [MTOT*EMBED];   // V projection, f32
__device__ float  g_att[MTOT*EMBED];  // attended, f32

__device__ __forceinline__ __half2 htanh2(__half2 x) {
    unsigned int xi = *reinterpret_cast<unsigned int*>(&x);
    unsigned int yi;
    asm("tanh.approx.f16x2 %0, %1;" : "=r"(yi) : "r"(xi));
    return *reinterpret_cast<__half2*>(&yi);
}

// FMA-pipe tanh: odd interpolant on |x|<=2.75 (clamped), t = xc * P(xc^2).
__device__ __forceinline__ __half2 poly_tanh2(__half2 x) {
    const __half2 lo = __float2half2_rn(-2.75f);
    const __half2 hi = __float2half2_rn( 2.75f);
    __half2 xc = __hmax2(lo, __hmin2(x, hi));
    __half2 u  = __hmul2(xc, xc);
    __half2 p  = __hfma2(u, __float2half2_rn(-6.3914e-05f), __float2half2_rn(1.60803e-03f));
    p = __hfma2(u, p, __float2half2_rn(-1.63146e-02f));
    p = __hfma2(u, p, __float2half2_rn( 8.88551e-02f));
    p = __hfma2(u, p, __float2half2_rn(-3.096166e-01f));
    p = __hfma2(u, p, __float2half2_rn( 9.975679e-01f));
    return __hmul2(xc, p);
}

__device__ __forceinline__ __half2 tanh_mixed(__half2 x, bool use_poly) {
    return use_poly ? poly_tanh2(x) : htanh2(x);
}

__device__ __forceinline__ float sumh2(__half2 h) {
    float2 f = __half22float2(h);
    return f.x + f.y;
}
__device__ __forceinline__ __half2 u2h(unsigned int u) {
    return *reinterpret_cast<__half2*>(&u);
}

// ---------------------------------------------------------------------------
// C[M,N] = A[M,K] @ W[N,K]^T + bias[N]  (torch Linear). grid.z picks problem;
// Hz != nullptr -> write half to Hz, else f32 to Cz.
// ---------------------------------------------------------------------------
__global__ __launch_bounds__(256) void gemm_bias3_kernel(
    const float* __restrict__ A0, const float* __restrict__ A1, const float* __restrict__ A2,
    const float* __restrict__ W0, const float* __restrict__ W1, const float* __restrict__ W2,
    const float* __restrict__ b0, const float* __restrict__ b1, const float* __restrict__ b2,
    float* __restrict__ C0, float* __restrict__ C1, float* __restrict__ C2,
    __half* __restrict__ H0, __half* __restrict__ H1, __half* __restrict__ H2,
    int M, int N, int K)
{
    const float* A; const float* W; const float* bias; float* C; __half* H;
    if (blockIdx.z == 0)      { A = A0; W = W0; bias = b0; C = C0; H = H0; }
    else if (blockIdx.z == 1) { A = A1; W = W1; bias = b1; C = C1; H = H1; }
    else                      { A = A2; W = W2; bias = b2; C = C2; H = H2; }

    __shared__ float As[2][16][68];
    __shared__ float Ws[2][16][68];
    const int tid = threadIdx.x;
    const int tx  = tid & 15;
    const int ty  = tid >> 4;
    const int n0  = blockIdx.x * 64;
    const int m0  = blockIdx.y * 64;

    const int lr = tid >> 2;
    const int lc = (tid & 3) << 2;
    const float* Ag = A + (size_t)(m0 + lr) * K + lc;
    const float* Wg = W + (size_t)(n0 + lr) * K + lc;

    float a00=0,a01=0,a02=0,a03=0, a10=0,a11=0,a12=0,a13=0;
    float a20=0,a21=0,a22=0,a23=0, a30=0,a31=0,a32=0,a33=0;

    float4 av = *(const float4*)(Ag);
    float4 wv = *(const float4*)(Wg);
    int buf = 0;

    for (int k0 = 0; k0 < K; k0 += 16) {
        As[buf][lc+0][lr] = av.x; As[buf][lc+1][lr] = av.y;
        As[buf][lc+2][lr] = av.z; As[buf][lc+3][lr] = av.w;
        Ws[buf][lc+0][lr] = wv.x; Ws[buf][lc+1][lr] = wv.y;
        Ws[buf][lc+2][lr] = wv.z; Ws[buf][lc+3][lr] = wv.w;
        __syncthreads();
        if (k0 + 16 < K) {
            av = *(const float4*)(Ag + k0 + 16);
            wv = *(const float4*)(Wg + k0 + 16);
        }
        #pragma unroll
        for (int k = 0; k < 16; k++) {
            float4 a = *(const float4*)&As[buf][k][ty*4];
            float4 w = *(const float4*)&Ws[buf][k][tx*4];
            a00 += a.x*w.x; a01 += a.x*w.y; a02 += a.x*w.z; a03 += a.x*w.w;
            a10 += a.y*w.x; a11 += a.y*w.y; a12 += a.y*w.z; a13 += a.y*w.w;
            a20 += a.z*w.x; a21 += a.z*w.y; a22 += a.z*w.z; a23 += a.z*w.w;
            a30 += a.w*w.x; a31 += a.w*w.y; a32 += a.w*w.z; a33 += a.w*w.w;
        }
        buf ^= 1;
    }

    const float4 bb = *(const float4*)&bias[n0 + tx*4];
    float r0x=a00+bb.x, r0y=a01+bb.y, r0z=a02+bb.z, r0w=a03+bb.w;
    float r1x=a10+bb.x, r1y=a11+bb.y, r1z=a12+bb.z, r1w=a13+bb.w;
    float r2x=a20+bb.x, r2y=a21+bb.y, r2z=a22+bb.z, r2w=a23+bb.w;
    float r3x=a30+bb.x, r3y=a31+bb.y, r3z=a32+bb.z, r3w=a33+bb.w;

    if (H) {
        __half* Hp = H + (size_t)(m0 + ty*4) * N + n0 + tx*4;
        __half2 p0, p1;
        p0 = __floats2half2_rn(r0x, r0y); p1 = __floats2half2_rn(r0z, r0w);
        *(uint2*)(Hp)       = make_uint2(*(unsigned int*)&p0, *(unsigned int*)&p1);
        p0 = __floats2half2_rn(r1x, r1y); p1 = __floats2half2_rn(r1z, r1w);
        *(uint2*)(Hp + N)   = make_uint2(*(unsigned int*)&p0, *(unsigned int*)&p1);
        p0 = __floats2half2_rn(r2x, r2y); p1 = __floats2half2_rn(r2z, r2w);
        *(uint2*)(Hp + 2*N) = make_uint2(*(unsigned int*)&p0, *(unsigned int*)&p1);
        p0 = __floats2half2_rn(r3x, r3y); p1 = __floats2half2_rn(r3z, r3w);
        *(uint2*)(Hp + 3*N) = make_uint2(*(unsigned int*)&p0, *(unsigned int*)&p1);
    } else {
        float* Cp = C + (size_t)(m0 + ty*4) * N + n0 + tx*4;
        float4 o;
        o.x=r0x; o.y=r0y; o.z=r0z; o.w=r0w; *(float4*)(Cp)       = o;
        o.x=r1x; o.y=r1y; o.z=r1z; o.w=r1w; *(float4*)(Cp + N)   = o;
        o.x=r2x; o.y=r2y; o.z=r2z; o.w=r2w; *(float4*)(Cp + 2*N) = o;
        o.x=r3x; o.y=r3y; o.z=r3z; o.w=r3w; *(float4*)(Cp + 3*N) = o;
    }
}

// ---------------------------------------------------------------------------
// Fused additive-attention kernel, v11:
//  * score: CKK=32 chunks, DOUBLE-BUFFERED K (2x4KB) -> 1 sync/chunk (16 total),
//    STS overlapped with compute. Hybrid MUFU/FMA tanh (f=3/8).
//  * AV: NO smem staging — direct __ldg of V (lanes 0-7 = one 32B sector,
//    broadcast x4; 512 independent loads/thread for MLP). Zero AV syncs.
// Smem floats: scT 10240 + K 2048 + qh 512 + vh 32 = 12832 (51328B) -> 4 blk/SM.
// ---------------------------------------------------------------------------
#define SCT_PITCH 20
#define CKK 32
#define NCHK (SKL/CKK)    /* 16 */
#define KBUF_FLOATS 2048  /* two 4KB half buffers */
#define ATTN_SMEM_FLOATS (SKL*SCT_PITCH + KBUF_FLOATS + 512 + 32)

__global__ __launch_bounds__(256, 4) void attn_kernel(
    const float* __restrict__ vparam, float* __restrict__ attn_out)
{
    extern __shared__ float smem[];
    float*  scT = smem;                           // [512][20]
    float*  uni = scT + SKL*SCT_PITCH;            // K double buffer
    __half* qh  = (__half*)(uni + KBUF_FLOATS);   // [16][64]
    __half* vh  = qh + 16*64;                     // [64]

    const int tid  = threadIdx.x;
    const int lane = tid & 31;
    const int warp = tid >> 5;
    const int b  = blockIdx.z;
    const int h  = blockIdx.y;
    const int q0t = blockIdx.x << 4;

    if (tid < 64) vh[tid] = __float2half(vparam[h*HDIM + tid]);
    {
        int row = tid >> 4;
        int seg = tid & 15;
        const uint2* src = (const uint2*)&g_Qh[((size_t)(b*SQL + q0t + row))*EMBED + h*HDIM + seg*4];
        *(uint2*)&qh[row*64 + seg*4] = *src;
    }

    const float scale = 0.125f;
    const int qa = warp*2;
    const int qb = qa + 1;

    // ====== score phase: 16 chunks of 32 k-rows, double-buffered K ==========
    {
        __half* kb0 = (__half*)uni;           // [32][64] swizzled
        __half* kb1 = kb0 + 2048;
        const int krow = tid >> 3;            // 0..31
        const int kseg = tid & 7;             // 16B segment of 128B row
        const int sseg = kseg ^ (krow & 7);   // swizzled segment
        const __half* Kg = &g_Kh[((size_t)(b*SKL))*EMBED + h*HDIM];

        uint4 kpre = *(const uint4*)(Kg + (size_t)krow*EMBED + kseg*8);
        *(uint4*)&kb0[krow*64 + sseg*8] = kpre;
        __syncthreads();

        for (int c = 0; c < NCHK; c++) {
            if (c + 1 < NCHK)
                kpre = *(const uint4*)(Kg + (size_t)((c+1)*CKK + krow)*EMBED + kseg*8);

            const uint4* qa4p = (const uint4*)&qh[qa*64];
            const uint4* qb4p = (const uint4*)&qh[qb*64];
            const uint4* vv4p = (const uint4*)vh;
            const __half* kr = ((c & 1) ? kb1 : kb0) + lane*64;
            const int sw = lane & 7;

            __half2 z = __float2half2_rn(0.f);
            __half2 accA0=z, accA1=z, accB0=z, accB1=z;

            #pragma unroll
            for (int db = 0; db < 8; db++) {
                const bool up = (db == 1) || (db == 4) || (db == 6);  // f=3/8 poly
                uint4 k4  = *(const uint4*)(kr + ((db ^ sw) * 8));
                uint4 qa4 = qa4p[db];
                uint4 qb4 = qb4p[db];
                uint4 vv4 = vv4p[db];

                __half2 k0=u2h(k4.x), k1=u2h(k4.y), k2=u2h(k4.z), k3=u2h(k4.w);
                __half2 qa0=u2h(qa4.x), qa1=u2h(qa4.y), qa2=u2h(qa4.z), qa3=u2h(qa4.w);
                __half2 qb0=u2h(qb4.x), qb1=u2h(qb4.y), qb2=u2h(qb4.z), qb3=u2h(qb4.w);
                __half2 v0=u2h(vv4.x), v1=u2h(vv4.y), v2=u2h(vv4.z), v3=u2h(vv4.w);

                accA0 = __hfma2(v0, tanh_mixed(__hadd2(qa0, k0), up), accA0);
                accB0 = __hfma2(v0, tanh_mixed(__hadd2(qb0, k0), up), accB0);
                accA1 = __hfma2(v1, tanh_mixed(__hadd2(qa1, k1), up), accA1);
                accB1 = __hfma2(v1, tanh_mixed(__hadd2(qb1, k1), up), accB1);
                accA0 = __hfma2(v2, tanh_mixed(__hadd2(qa2, k2), up), accA0);
                accB0 = __hfma2(v2, tanh_mixed(__hadd2(qb2, k2), up), accB0);
                accA1 = __hfma2(v3, tanh_mixed(__hadd2(qa3, k3), up), accA1);
                accB1 = __hfma2(v3, tanh_mixed(__hadd2(qb3, k3), up), accB1);
            }

            scT[(c*CKK + lane)*SCT_PITCH + qa] = (sumh2(accA0) + sumh2(accA1)) * scale;
            scT[(c*CKK + lane)*SCT_PITCH + qb] = (sumh2(accB0) + sumh2(accB1)) * scale;

            if (c + 1 < NCHK) {
                // other buffer: last read two chunks ago — safe to fill now
                __half* kw = ((c & 1) ? kb0 : kb1);
                *(uint4*)&kw[krow*64 + sseg*8] = kpre;
            }
            __syncthreads();
        }
    }

    // ---------------- softmax (each warp: 2 rows of 512) ----------------
    #pragma unroll
    for (int qq = 0; qq < 2; qq++) {
        const int q = qa + qq;
        float x[16];
        #pragma unroll
        for (int j = 0; j < 16; j++) x[j] = scT[(lane + 32*j)*SCT_PITCH + q];
        float m = -1e30f;
        #pragma unroll
        for (int j = 0; j < 16; j++) m = fmaxf(m, x[j]);
        #pragma unroll
        for (int o = 16; o; o >>= 1) m = fmaxf(m, __shfl_xor_sync(0xffffffffu, m, o));
        float s = 0.f;
        #pragma unroll
        for (int j = 0; j < 16; j++) { x[j] = __expf(x[j] - m); s += x[j]; }
        #pragma unroll
        for (int o = 16; o; o >>= 1) s += __shfl_xor_sync(0xffffffffu, s, o);
        const float r = 1.0f / s;
        float* arow = attn_out + ((size_t)((b*HEADS + h)*SQL + q0t + q))*SKL;
        #pragma unroll
        for (int j = 0; j < 16; j++) {
            float p = x[j] * r;
            scT[(lane + 32*j)*SCT_PITCH + q] = p;
            arow[lane + 32*j] = p;
        }
    }
    __syncthreads();   // all probs visible for AV

    // ========= AV phase: direct-LDG V, zero syncs =========
    {
        const int g  = lane >> 3;            // q-group: q = 4g..4g+3
        const int dl = warp*8 + (lane & 7);  // this thread's d
        const float* Vp = &g_V[((size_t)(b*SKL))*EMBED + h*HDIM + dl];
        const float* pb = scT + 4*g;

        float a0=0.f, a1=0.f, a2=0.f, a3=0.f;
        #pragma unroll 8
        for (int k = 0; k < SKL; k++) {
            float4 p = *(const float4*)(pb + k*SCT_PITCH);
            float  v = __ldg(Vp + (size_t)k*EMBED);
            a0 += p.x*v; a1 += p.y*v; a2 += p.z*v; a3 += p.w*v;
        }

        float* abase = &g_att[((size_t)(b*SQL + q0t + 4*g))*EMBED + h*HDIM + dl];
        abase[0]       = a0;
        abase[EMBED]   = a1;
        abase[2*EMBED] = a2;
        abase[3*EMBED] = a3;
    }
}

// ---------------------------------------------------------------------------
extern "C" void kernel_launch(void* const* d_in, const int* in_sizes, int n_in,
                              void* d_out, int out_size)
{
    (void)in_sizes; (void)n_in; (void)out_size;
    const float* query = (const float*)d_in[0];
    const float* key_  = (const float*)d_in[1];
    const float* value = (const float*)d_in[2];
    const float* Wq = (const float*)d_in[3];
    const float* bq = (const float*)d_in[4];
    const float* Wk = (const float*)d_in[5];
    const float* bk = (const float*)d_in[6];
    const float* Wv = (const float*)d_in[7];
    const float* bv = (const float*)d_in[8];
    const float* vp = (const float*)d_in[9];
    const float* Wo = (const float*)d_in[10];
    const float* bo = (const float*)d_in[11];

    float* out  = (float*)d_out;                 // [B, SQ, EMBED]
    float* attn = out + (size_t)MTOT * EMBED;    // [B, H, SQ, SK]

    __half *gQh, *gKh;
    float *gV, *gA;
    cudaGetSymbolAddress((void**)&gQh, g_Qh);
    cudaGetSymbolAddress((void**)&gKh, g_Kh);
    cudaGetSymbolAddress((void**)&gV,  g_V);
    cudaGetSymbolAddress((void**)&gA,  g_att);

    const int smem_bytes = ATTN_SMEM_FLOATS * (int)sizeof(float);
    cudaFuncSetAttribute(attn_kernel, cudaFuncAttributeMaxDynamicSharedMemorySize, smem_bytes);

    dim3 ggrid3(EMBED/64, MTOT/64, 3);
    gemm_bias3_kernel<<<ggrid3, 256>>>(query, key_, value,
                                       Wq, Wk, Wv,
                                       bq, bk, bv,
                                       nullptr, nullptr, gV,
                                       gQh, gKh, nullptr,
                                       MTOT, EMBED, EMBED);

    dim3 agrid(SQL/16, HEADS, BATCH);  // (32, 4, 4)
    attn_kernel<<<agrid, 256, smem_bytes>>>(vp, attn);

    dim3 ggrid(EMBED/64, MTOT/64, 1);
    gemm_bias3_kernel<<<ggrid, 256>>>(gA, gA, gA,
                                      Wo, Wo, Wo,
                                      bo, bo, bo,
                                      out, out, out,
                                      nullptr, nullptr, nullptr,
                                      MTOT, EMBED, EMBED);
}

// round 15
// speedup vs baseline: 1.1964x; 1.1964x over previous
#include <cuda_runtime.h>
#include <cuda_fp16.h>
#include <cstdint>

#define EMBED 256
#define HEADS 4
#define HDIM  64
#define BATCH 4
#define SQL   512
#define SKL   512
#define MTOT  (BATCH*SQL)   /* 2048 */

// Scratch (allocation-free rule: __device__ globals)
__device__ __half g_Qh[MTOT*EMBED];   // Q projection, half
__device__ __half g_Kh[MTOT*EMBED];   // K projection, half
__device__ float  g_V [MTOT*EMBED];   // V projection, f32
__device__ float  g_att[MTOT*EMBED];  // attended, f32

__device__ __forceinline__ __half2 htanh2(__half2 x) {
    unsigned int xi = *reinterpret_cast<unsigned int*>(&x);
    unsigned int yi;
    asm("tanh.approx.f16x2 %0, %1;" : "=r"(yi) : "r"(xi));
    return *reinterpret_cast<__half2*>(&yi);
}

// FMA-pipe tanh: odd interpolant on |x|<=2.75 (clamped), t = xc * P(xc^2).
__device__ __forceinline__ __half2 poly_tanh2(__half2 x) {
    const __half2 lo = __float2half2_rn(-2.75f);
    const __half2 hi = __float2half2_rn( 2.75f);
    __half2 xc = __hmax2(lo, __hmin2(x, hi));
    __half2 u  = __hmul2(xc, xc);
    __half2 p  = __hfma2(u, __float2half2_rn(-6.3914e-05f), __float2half2_rn(1.60803e-03f));
    p = __hfma2(u, p, __float2half2_rn(-1.63146e-02f));
    p = __hfma2(u, p, __float2half2_rn( 8.88551e-02f));
    p = __hfma2(u, p, __float2half2_rn(-3.096166e-01f));
    p = __hfma2(u, p, __float2half2_rn( 9.975679e-01f));
    return __hmul2(xc, p);
}

__device__ __forceinline__ __half2 tanh_mixed(__half2 x, bool use_poly) {
    return use_poly ? poly_tanh2(x) : htanh2(x);
}

__device__ __forceinline__ float sumh2(__half2 h) {
    float2 f = __half22float2(h);
    return f.x + f.y;
}
__device__ __forceinline__ __half2 u2h(unsigned int u) {
    return *reinterpret_cast<__half2*>(&u);
}
__device__ __forceinline__ void cp_async16_ca(void* smem_dst, const void* gsrc) {
    unsigned int saddr = (unsigned int)__cvta_generic_to_shared(smem_dst);
    asm volatile("cp.async.ca.shared.global [%0], [%1], 16;\n" :: "r"(saddr), "l"(gsrc));
}
__device__ __forceinline__ void cp_commit() {
    asm volatile("cp.async.commit_group;\n");
}
template<int N>
__device__ __forceinline__ void cp_wait() {
    asm volatile("cp.async.wait_group %0;\n" :: "n"(N));
}

// ---- tensor-core helpers ----
__device__ __forceinline__ void ldm_x4(uint32_t addr, uint32_t &r0, uint32_t &r1,
                                       uint32_t &r2, uint32_t &r3) {
    asm volatile("ldmatrix.sync.aligned.m8n8.x4.shared.b16 {%0,%1,%2,%3}, [%4];"
                 : "=r"(r0), "=r"(r1), "=r"(r2), "=r"(r3) : "r"(addr));
}
__device__ __forceinline__ void mma16816(float* d, const uint32_t* a,
                                         uint32_t b0, uint32_t b1) {
    asm volatile("mma.sync.aligned.m16n8k16.row.col.f32.f16.f16.f32 "
                 "{%0,%1,%2,%3}, {%4,%5,%6,%7}, {%8,%9}, {%0,%1,%2,%3};"
                 : "+f"(d[0]), "+f"(d[1]), "+f"(d[2]), "+f"(d[3])
                 : "r"(a[0]), "r"(a[1]), "r"(a[2]), "r"(a[3]), "r"(b0), "r"(b1));
}

// ---------------------------------------------------------------------------
// HMMA GEMM: C[M,N] = A[M,K] @ W[N,K]^T + bias[N], M=2048, N=K=256.
// Block 128 thr (4 warps), tile 64x64, k-chunk 32, double-buffered smem.
// split=0: single-half mma (for Q/K, outputs rounded to half anyway).
// split=1: Markidis hi/lo split, 3 mmas (for V and output proj, ~f32 accuracy).
// grid.z picks problem; Hz != nullptr -> half output, else f32 to Cz.
// smem layout (halves): region[buf][part][row 0..63][32], row pitch 64B,
// 4 segs/row, swizzle seg^((row>>1)&3). A at 0, B at 16KB. Total 32KB.
// ---------------------------------------------------------------------------
__global__ __launch_bounds__(128) void hgemm_bias3_kernel(
    const float* __restrict__ A0, const float* __restrict__ A1, const float* __restrict__ A2,
    const float* __restrict__ W0, const float* __restrict__ W1, const float* __restrict__ W2,
    const float* __restrict__ b0, const float* __restrict__ b1, const float* __restrict__ b2,
    float* __restrict__ C0, float* __restrict__ C1, float* __restrict__ C2,
    __half* __restrict__ H0, __half* __restrict__ H1, __half* __restrict__ H2,
    int s0, int s1, int s2,
    int M, int N, int K)
{
    const float* A; const float* W; const float* bias; float* C; __half* H; int split;
    if (blockIdx.z == 0)      { A = A0; W = W0; bias = b0; C = C0; H = H0; split = s0; }
    else if (blockIdx.z == 1) { A = A1; W = W1; bias = b1; C = C1; H = H1; split = s1; }
    else                      { A = A2; W = W2; bias = b2; C = C2; H = H2; split = s2; }

    __shared__ __half sA[2][2][64][32];   // [buf][hi/lo][row][col]
    __shared__ __half sB[2][2][64][32];

    const int tid  = threadIdx.x;
    const int lane = tid & 31;
    const int w    = tid >> 5;
    const int n0   = blockIdx.x * 64;
    const int m0   = blockIdx.y * 64;

    const uint32_t sA_u = (uint32_t)__cvta_generic_to_shared(&sA[0][0][0][0]);
    const uint32_t sB_u = (uint32_t)__cvta_generic_to_shared(&sB[0][0][0][0]);

    // staging mapping: thread t -> row = t>>1 (0..63), half-row hs = t&1 (cols hs*16..+15)
    const int srow = tid >> 1;
    const int hs   = tid & 1;
    const float* Ag = A + (size_t)(m0 + srow) * K + hs * 16;
    const float* Wg = W + (size_t)(n0 + srow) * K + hs * 16;

    float4 af[4], bf[4];   // prefetch regs: 16 floats each matrix

    // convert+store one matrix-half into smem region (part-strided)
    auto cvt_sts = [&](const float4* f, uint32_t base_u, int buf, int do_split) {
        __half hh[16]; float lf[16];
        const float* xs = (const float*)f;
        #pragma unroll
        for (int i = 0; i < 16; i++) {
            hh[i] = __float2half_rn(xs[i]);
            lf[i] = xs[i] - __half2float(hh[i]);
        }
        const uint32_t rowb = (uint32_t)(buf*8192 + srow*64);
        #pragma unroll
        for (int g = 0; g < 2; g++) {
            int seg = hs*2 + g;
            int sw  = seg ^ ((srow >> 1) & 3);
            uint4 u;
            __half2 p;
            p = __halves2half2(hh[8*g+0], hh[8*g+1]); u.x = *(unsigned*)&p;
            p = __halves2half2(hh[8*g+2], hh[8*g+3]); u.y = *(unsigned*)&p;
            p = __halves2half2(hh[8*g+4], hh[8*g+5]); u.z = *(unsigned*)&p;
            p = __halves2half2(hh[8*g+6], hh[8*g+7]); u.w = *(unsigned*)&p;
            *(uint4*)__cvta_shared_to_generic(base_u + rowb + sw*16) = u;
            if (do_split) {
                __half ll[8];
                #pragma unroll
                for (int i = 0; i < 8; i++) ll[i] = __float2half_rn(lf[8*g+i]);
                p = __halves2half2(ll[0], ll[1]); u.x = *(unsigned*)&p;
                p = __halves2half2(ll[2], ll[3]); u.y = *(unsigned*)&p;
                p = __halves2half2(ll[4], ll[5]); u.z = *(unsigned*)&p;
                p = __halves2half2(ll[6], ll[7]); u.w = *(unsigned*)&p;
                *(uint4*)__cvta_shared_to_generic(base_u + 4096 + rowb + sw*16) = u;
            }
        }
    };

    // ---- prime chunk 0 ----
    #pragma unroll
    for (int i = 0; i < 4; i++) { af[i] = *(const float4*)(Ag + i*4); bf[i] = *(const float4*)(Wg + i*4); }
    cvt_sts(af, sA_u, 0, split);
    cvt_sts(bf, sB_u, 0, split);
    __syncthreads();

    float d[8][4];
    #pragma unroll
    for (int i = 0; i < 8; i++) { d[i][0]=0.f; d[i][1]=0.f; d[i][2]=0.f; d[i][3]=0.f; }

    const int lrow = lane & 15;
    const int lks  = lane >> 4;        // 0/1 -> k segment within k16
    const int arow = w*16 + lrow;
    const uint32_t aswb = (uint32_t)((arow >> 1) & 3);

    for (int c = 0; c < 8; c++) {
        if (c + 1 < 8) {
            #pragma unroll
            for (int i = 0; i < 4; i++) {
                af[i] = *(const float4*)(Ag + (c+1)*32 + i*4);
                bf[i] = *(const float4*)(Wg + (c+1)*32 + i*4);
            }
        }
        const uint32_t bufo = (uint32_t)((c & 1) * 8192);

        #pragma unroll
        for (int ks = 0; ks < 2; ks++) {
            const uint32_t seg = (uint32_t)(ks*2 + lks);
            uint32_t ah[4], al[4];
            {
                uint32_t sw = seg ^ aswb;
                ldm_x4(sA_u + bufo + (uint32_t)arow*64 + sw*16, ah[0], ah[1], ah[2], ah[3]);
                if (split)
                    ldm_x4(sA_u + 4096 + bufo + (uint32_t)arow*64 + sw*16, al[0], al[1], al[2], al[3]);
            }
            #pragma unroll
            for (int bp = 0; bp < 4; bp++) {
                const int brow = bp*16 + lrow;
                const uint32_t sw = seg ^ (uint32_t)((brow >> 1) & 3);
                uint32_t bh0, bh1, bh2, bh3;
                ldm_x4(sB_u + bufo + (uint32_t)brow*64 + sw*16, bh0, bh1, bh2, bh3);
                mma16816(d[2*bp],   ah, bh0, bh2);
                mma16816(d[2*bp+1], ah, bh1, bh3);
                if (split) {
                    uint32_t bl0, bl1, bl2, bl3;
                    ldm_x4(sB_u + 4096 + bufo + (uint32_t)brow*64 + sw*16, bl0, bl1, bl2, bl3);
                    mma16816(d[2*bp],   ah, bl0, bl2);
                    mma16816(d[2*bp+1], ah, bl1, bl3);
                    mma16816(d[2*bp],   al, bh0, bh2);
                    mma16816(d[2*bp+1], al, bh1, bh3);
                }
            }
        }

        if (c + 1 < 8) {
            cvt_sts(af, sA_u, (c+1) & 1, split);
            cvt_sts(bf, sB_u, (c+1) & 1, split);
        }
        __syncthreads();
    }

    // ---- epilogue: bias + store ----
    const int mrow = m0 + w*16 + (lane >> 2);
    const int nc0  = n0 + 2*(lane & 3);
    #pragma unroll
    for (int nt = 0; nt < 8; nt++) {
        const int n = nc0 + nt*8;
        float2 bb = *(const float2*)&bias[n];
        float v0 = d[nt][0] + bb.x, v1 = d[nt][1] + bb.y;
        float v2 = d[nt][2] + bb.x, v3 = d[nt][3] + bb.y;
        if (H) {
            __half2 p0 = __floats2half2_rn(v0, v1);
            __half2 p1 = __floats2half2_rn(v2, v3);
            *(unsigned*)&H[(size_t)mrow*N + n]     = *(unsigned*)&p0;
            *(unsigned*)&H[(size_t)(mrow+8)*N + n] = *(unsigned*)&p1;
        } else {
            *(float2*)&C[(size_t)mrow*N + n]     = make_float2(v0, v1);
            *(float2*)&C[(size_t)(mrow+8)*N + n] = make_float2(v2, v3);
        }
    }
}

// ---------------------------------------------------------------------------
// Fused additive-attention kernel (R13 structure, best known: 129.7us total):
//  * score: CKK=32 (16 chunks), 1 k-row/lane, reg-prefetch, hybrid tanh f=3/8.
//  * AV: CKV=32 staged reg-prefetch, chunk 0 via cp.async over softmax.
// ---------------------------------------------------------------------------
#define SCT_PITCH 20
#define CKK 32
#define NCHK (SKL/CKK)    /* 16 */
#define CKV 32
#define NCHV (SKL/CKV)    /* 16 */
#define VF_PITCH 68
#define UNION_FLOATS 2176
#define ATTN_SMEM_FLOATS (SKL*SCT_PITCH + UNION_FLOATS + 512 + 32)

__global__ __launch_bounds__(256, 4) void attn_kernel(
    const float* __restrict__ vparam, float* __restrict__ attn_out)
{
    extern __shared__ float smem[];
    float*  scT = smem;                           // [512][20]
    float*  uni = scT + SKL*SCT_PITCH;            // union staging
    __half* qh  = (__half*)(uni + UNION_FLOATS);  // [16][64]
    __half* vh  = qh + 16*64;                     // [64]

    const int tid  = threadIdx.x;
    const int lane = tid & 31;
    const int warp = tid >> 5;
    const int b  = blockIdx.z;
    const int h  = blockIdx.y;
    const int q0t = blockIdx.x << 4;

    if (tid < 64) vh[tid] = __float2half(vparam[h*HDIM + tid]);
    {
        int row = tid >> 4;
        int seg = tid & 15;
        const uint2* src = (const uint2*)&g_Qh[((size_t)(b*SQL + q0t + row))*EMBED + h*HDIM + seg*4];
        *(uint2*)&qh[row*64 + seg*4] = *src;
    }

    const float scale = 0.125f;
    const int qa = warp*2;
    const int qb = qa + 1;

    // ====== score phase: 16 chunks of 32 k-rows, 1 k-row/lane, reg-prefetch ==
    {
        __half* kb = (__half*)uni;            // [32 rows][64 halves] swizzled
        const int krow = tid >> 3;            // 0..31
        const int kseg = tid & 7;             // 16B segment of 128B row
        const int sseg = kseg ^ (krow & 7);   // swizzled segment
        const __half* Kg = &g_Kh[((size_t)(b*SKL))*EMBED + h*HDIM];

        uint4 kpre = *(const uint4*)(Kg + (size_t)krow*EMBED + kseg*8);
        *(uint4*)&kb[krow*64 + sseg*8] = kpre;
        __syncthreads();

        for (int c = 0; c < NCHK; c++) {
            if (c + 1 < NCHK)
                kpre = *(const uint4*)(Kg + (size_t)((c+1)*CKK + krow)*EMBED + kseg*8);

            const uint4* qa4p = (const uint4*)&qh[qa*64];
            const uint4* qb4p = (const uint4*)&qh[qb*64];
            const uint4* vv4p = (const uint4*)vh;
            const __half* kr = kb + lane*64;
            const int sw = lane & 7;

            __half2 z = __float2half2_rn(0.f);
            __half2 accA0=z, accA1=z, accB0=z, accB1=z;

            #pragma unroll
            for (int db = 0; db < 8; db++) {
                const bool up = (db == 1) || (db == 4) || (db == 6);  // f=3/8 poly
                uint4 k4  = *(const uint4*)(kr + ((db ^ sw) * 8));
                uint4 qa4 = qa4p[db];
                uint4 qb4 = qb4p[db];
                uint4 vv4 = vv4p[db];

                __half2 k0=u2h(k4.x), k1=u2h(k4.y), k2=u2h(k4.z), k3=u2h(k4.w);
                __half2 qa0=u2h(qa4.x), qa1=u2h(qa4.y), qa2=u2h(qa4.z), qa3=u2h(qa4.w);
                __half2 qb0=u2h(qb4.x), qb1=u2h(qb4.y), qb2=u2h(qb4.z), qb3=u2h(qb4.w);
                __half2 v0=u2h(vv4.x), v1=u2h(vv4.y), v2=u2h(vv4.z), v3=u2h(vv4.w);

                accA0 = __hfma2(v0, tanh_mixed(__hadd2(qa0, k0), up), accA0);
                accB0 = __hfma2(v0, tanh_mixed(__hadd2(qb0, k0), up), accB0);
                accA1 = __hfma2(v1, tanh_mixed(__hadd2(qa1, k1), up), accA1);
                accB1 = __hfma2(v1, tanh_mixed(__hadd2(qb1, k1), up), accB1);
                accA0 = __hfma2(v2, tanh_mixed(__hadd2(qa2, k2), up), accA0);
                accB0 = __hfma2(v2, tanh_mixed(__hadd2(qb2, k2), up), accB0);
                accA1 = __hfma2(v3, tanh_mixed(__hadd2(qa3, k3), up), accA1);
                accB1 = __hfma2(v3, tanh_mixed(__hadd2(qb3, k3), up), accB1);
            }

            scT[(c*CKK + lane)*SCT_PITCH + qa] = (sumh2(accA0) + sumh2(accA1)) * scale;
            scT[(c*CKK + lane)*SCT_PITCH + qb] = (sumh2(accB0) + sumh2(accB1)) * scale;

            __syncthreads();
            if (c + 1 < NCHK) {
                *(uint4*)&kb[krow*64 + sseg*8] = kpre;
                __syncthreads();
            }
        }
    }
    __syncthreads();

    // ---- prime V chunk 0 (32 rows) via cp.async, overlapping softmax ----
    {
        const int vrow  = tid >> 4;          // 0..15
        const int vseg4 = (tid & 15) << 2;   // 0,4,..,60
        const float* Vg = &g_V[((size_t)(b*SKL))*EMBED + h*HDIM];
        cp_async16_ca(&uni[vrow*VF_PITCH + vseg4],      Vg + (size_t)vrow*EMBED + vseg4);
        cp_async16_ca(&uni[(vrow+16)*VF_PITCH + vseg4], Vg + (size_t)(vrow+16)*EMBED + vseg4);
        cp_commit();
    }

    // ---------------- softmax (each warp: 2 rows of 512) ----------------
    #pragma unroll
    for (int qq = 0; qq < 2; qq++) {
        const int q = qa + qq;
        float x[16];
        #pragma unroll
        for (int j = 0; j < 16; j++) x[j] = scT[(lane + 32*j)*SCT_PITCH + q];
        float m = -1e30f;
        #pragma unroll
        for (int j = 0; j < 16; j++) m = fmaxf(m, x[j]);
        #pragma unroll
        for (int o = 16; o; o >>= 1) m = fmaxf(m, __shfl_xor_sync(0xffffffffu, m, o));
        float s = 0.f;
        #pragma unroll
        for (int j = 0; j < 16; j++) { x[j] = __expf(x[j] - m); s += x[j]; }
        #pragma unroll
        for (int o = 16; o; o >>= 1) s += __shfl_xor_sync(0xffffffffu, s, o);
        const float r = 1.0f / s;
        float* arow = attn_out + ((size_t)((b*HEADS + h)*SQL + q0t + q))*SKL;
        #pragma unroll
        for (int j = 0; j < 16; j++) {
            float p = x[j] * r;
            scT[(lane + 32*j)*SCT_PITCH + q] = p;
            arow[lane + 32*j] = p;
        }
    }

    // ========= AV phase: 16 chunks of 32 k-rows, reg-prefetch =========
    {
        float* kvf = uni;                    // [32][68]
        const int vrow  = tid >> 4;
        const int vseg4 = (tid & 15) << 2;
        const float* Vg = &g_V[((size_t)(b*SKL))*EMBED + h*HDIM];
        const int g  = lane >> 3;            // q-group: q = 4g..4g+3
        const int dl = warp*8 + (lane & 7);  // this thread's d

        cp_wait<0>();
        __syncthreads();                     // chunk 0 resident

        float4 vpre[2];
        float a0=0.f, a1=0.f, a2=0.f, a3=0.f;
        for (int c = 0; c < NCHV; c++) {
            if (c + 1 < NCHV) {
                #pragma unroll
                for (int it = 0; it < 2; it++)
                    vpre[it] = *(const float4*)(Vg + ((size_t)((c+1)*CKV + vrow + it*16))*EMBED + vseg4);
            }
            const float* pb  = &scT[(c*CKV)*SCT_PITCH + 4*g];
            const float* vbp = kvf + dl;
            #pragma unroll 8
            for (int kp = 0; kp < CKV; kp++) {
                float4 p = *(const float4*)(pb + kp*SCT_PITCH);
                float  v = vbp[kp*VF_PITCH];
                a0 += p.x*v; a1 += p.y*v; a2 += p.z*v; a3 += p.w*v;
            }
            __syncthreads();
            if (c + 1 < NCHV) {
                #pragma unroll
                for (int it = 0; it < 2; it++)
                    *(float4*)&kvf[(vrow + it*16)*VF_PITCH + vseg4] = vpre[it];
                __syncthreads();
            }
        }

        float* abase = &g_att[((size_t)(b*SQL + q0t + 4*g))*EMBED + h*HDIM + dl];
        abase[0]       = a0;
        abase[EMBED]   = a1;
        abase[2*EMBED] = a2;
        abase[3*EMBED] = a3;
    }
}

// ---------------------------------------------------------------------------
extern "C" void kernel_launch(void* const* d_in, const int* in_sizes, int n_in,
                              void* d_out, int out_size)
{
    (void)in_sizes; (void)n_in; (void)out_size;
    const float* query = (const float*)d_in[0];
    const float* key_  = (const float*)d_in[1];
    const float* value = (const float*)d_in[2];
    const float* Wq = (const float*)d_in[3];
    const float* bq = (const float*)d_in[4];
    const float* Wk = (const float*)d_in[5];
    const float* bk = (const float*)d_in[6];
    const float* Wv = (const float*)d_in[7];
    const float* bv = (const float*)d_in[8];
    const float* vp = (const float*)d_in[9];
    const float* Wo = (const float*)d_in[10];
    const float* bo = (const float*)d_in[11];

    float* out  = (float*)d_out;                 // [B, SQ, EMBED]
    float* attn = out + (size_t)MTOT * EMBED;    // [B, H, SQ, SK]

    __half *gQh, *gKh;
    float *gV, *gA;
    cudaGetSymbolAddress((void**)&gQh, g_Qh);
    cudaGetSymbolAddress((void**)&gKh, g_Kh);
    cudaGetSymbolAddress((void**)&gV,  g_V);
    cudaGetSymbolAddress((void**)&gA,  g_att);

    const int smem_bytes = ATTN_SMEM_FLOATS * (int)sizeof(float);
    cudaFuncSetAttribute(attn_kernel, cudaFuncAttributeMaxDynamicSharedMemorySize, smem_bytes);

    // Q,K: half out, single mma. V: f32 out, split mma.
    dim3 ggrid3(EMBED/64, MTOT/64, 3);   // (4, 32, 3)
    hgemm_bias3_kernel<<<ggrid3, 128>>>(query, key_, value,
                                        Wq, Wk, Wv,
                                        bq, bk, bv,
                                        nullptr, nullptr, gV,
                                        gQh, gKh, nullptr,
                                        0, 0, 1,
                                        MTOT, EMBED, EMBED);

    dim3 agrid(SQL/16, HEADS, BATCH);  // (32, 4, 4)
    attn_kernel<<<agrid, 256, smem_bytes>>>(vp, attn);

    // Output projection: f32 out, split mma.
    dim3 ggrid(EMBED/64, MTOT/64, 1);
    hgemm_bias3_kernel<<<ggrid, 128>>>(gA, gA, gA,
                                       Wo, Wo, Wo,
                                       bo, bo, bo,
                                       out, out, out,
                                       nullptr, nullptr, nullptr,
                                       1, 1, 1,
                                       MTOT, EMBED, EMBED);
}

// round 16
// speedup vs baseline: 1.2379x; 1.0346x over previous
#include <cuda_runtime.h>
#include <cuda_fp16.h>
#include <cstdint>

#define EMBED 256
#define HEADS 4
#define HDIM  64
#define BATCH 4
#define SQL   512
#define SKL   512
#define MTOT  (BATCH*SQL)   /* 2048 */

// Scratch (allocation-free rule: __device__ globals)
__device__ __half g_Qh[MTOT*EMBED];   // Q projection, half
__device__ __half g_Kh[MTOT*EMBED];   // K projection, half
__device__ float  g_V [MTOT*EMBED];   // V projection, f32
__device__ float  g_att[MTOT*EMBED];  // attended, f32

__device__ __forceinline__ __half2 htanh2(__half2 x) {
    unsigned int xi = *reinterpret_cast<unsigned int*>(&x);
    unsigned int yi;
    asm("tanh.approx.f16x2 %0, %1;" : "=r"(yi) : "r"(xi));
    return *reinterpret_cast<__half2*>(&yi);
}

// FMA-pipe tanh: odd interpolant on |x|<=2.75 (clamped), t = xc * P(xc^2).
__device__ __forceinline__ __half2 poly_tanh2(__half2 x) {
    const __half2 lo = __float2half2_rn(-2.75f);
    const __half2 hi = __float2half2_rn( 2.75f);
    __half2 xc = __hmax2(lo, __hmin2(x, hi));
    __half2 u  = __hmul2(xc, xc);
    __half2 p  = __hfma2(u, __float2half2_rn(-6.3914e-05f), __float2half2_rn(1.60803e-03f));
    p = __hfma2(u, p, __float2half2_rn(-1.63146e-02f));
    p = __hfma2(u, p, __float2half2_rn( 8.88551e-02f));
    p = __hfma2(u, p, __float2half2_rn(-3.096166e-01f));
    p = __hfma2(u, p, __float2half2_rn( 9.975679e-01f));
    return __hmul2(xc, p);
}

__device__ __forceinline__ __half2 tanh_mixed(__half2 x, bool use_poly) {
    return use_poly ? poly_tanh2(x) : htanh2(x);
}

__device__ __forceinline__ float sumh2(__half2 h) {
    float2 f = __half22float2(h);
    return f.x + f.y;
}
__device__ __forceinline__ __half2 u2h(unsigned int u) {
    return *reinterpret_cast<__half2*>(&u);
}
__device__ __forceinline__ void cp_async16_ca(void* smem_dst, const void* gsrc) {
    unsigned int saddr = (unsigned int)__cvta_generic_to_shared(smem_dst);
    asm volatile("cp.async.ca.shared.global [%0], [%1], 16;\n" :: "r"(saddr), "l"(gsrc));
}
__device__ __forceinline__ void cp_commit() {
    asm volatile("cp.async.commit_group;\n");
}
template<int N>
__device__ __forceinline__ void cp_wait() {
    asm volatile("cp.async.wait_group %0;\n" :: "n"(N));
}

// ---- tensor-core helpers ----
__device__ __forceinline__ void ldm_x4(uint32_t addr, uint32_t &r0, uint32_t &r1,
                                       uint32_t &r2, uint32_t &r3) {
    asm volatile("ldmatrix.sync.aligned.m8n8.x4.shared.b16 {%0,%1,%2,%3}, [%4];"
                 : "=r"(r0), "=r"(r1), "=r"(r2), "=r"(r3) : "r"(addr));
}
__device__ __forceinline__ void mma16816(float* d, const uint32_t* a,
                                         uint32_t b0, uint32_t b1) {
    asm volatile("mma.sync.aligned.m16n8k16.row.col.f32.f16.f16.f32 "
                 "{%0,%1,%2,%3}, {%4,%5,%6,%7}, {%8,%9}, {%0,%1,%2,%3};"
                 : "+f"(d[0]), "+f"(d[1]), "+f"(d[2]), "+f"(d[3])
                 : "r"(a[0]), "r"(a[1]), "r"(a[2]), "r"(a[3]), "r"(b0), "r"(b1));
}

// ---------------------------------------------------------------------------
// HMMA GEMM v2: 256 threads (8 warps), 64x64 tile; warp (wr=w&3, wc=w>>2)
// owns a 16x32 sub-tile. k-chunk 32, double-buffered smem, same swizzle as v1.
// split=0: single-half mma (Q/K). split=1: Markidis hi/lo, 3 mmas (V, out).
// smem: sA/sB [buf][hi/lo][64][32] halves, 16KB each, 32KB total.
// ---------------------------------------------------------------------------
__global__ __launch_bounds__(256) void hgemm_bias3_kernel(
    const float* __restrict__ A0, const float* __restrict__ A1, const float* __restrict__ A2,
    const float* __restrict__ W0, const float* __restrict__ W1, const float* __restrict__ W2,
    const float* __restrict__ b0, const float* __restrict__ b1, const float* __restrict__ b2,
    float* __restrict__ C0, float* __restrict__ C1, float* __restrict__ C2,
    __half* __restrict__ H0, __half* __restrict__ H1, __half* __restrict__ H2,
    int s0, int s1, int s2,
    int M, int N, int K)
{
    const float* A; const float* W; const float* bias; float* C; __half* H; int split;
    if (blockIdx.z == 0)      { A = A0; W = W0; bias = b0; C = C0; H = H0; split = s0; }
    else if (blockIdx.z == 1) { A = A1; W = W1; bias = b1; C = C1; H = H1; split = s1; }
    else                      { A = A2; W = W2; bias = b2; C = C2; H = H2; split = s2; }

    __shared__ __half sA[2][2][64][32];   // [buf][hi/lo][row][col]
    __shared__ __half sB[2][2][64][32];

    const int tid  = threadIdx.x;
    const int lane = tid & 31;
    const int w    = tid >> 5;           // 0..7
    const int wr   = w & 3;              // m sub-tile
    const int wc   = w >> 2;             // n half (0/1)
    const int n0   = blockIdx.x * 64;
    const int m0   = blockIdx.y * 64;

    const uint32_t sA_u = (uint32_t)__cvta_generic_to_shared(&sA[0][0][0][0]);
    const uint32_t sB_u = (uint32_t)__cvta_generic_to_shared(&sB[0][0][0][0]);

    // staging: thread t -> row = t>>2 (0..63), seg hs = t&3 (8 halves = 16B)
    const int srow = tid >> 2;
    const int hs   = tid & 3;
    const int ssw  = hs ^ ((srow >> 1) & 3);
    const float* Ag = A + (size_t)(m0 + srow) * K + hs * 8;
    const float* Wg = W + (size_t)(n0 + srow) * K + hs * 8;

    float4 af[2], bf[2];   // prefetch: 8 floats per matrix per thread

    auto cvt_sts = [&](const float4* f, uint32_t base_u, int buf, int do_split) {
        const float* xs = (const float*)f;
        __half hh[8];
        #pragma unroll
        for (int i = 0; i < 8; i++) hh[i] = __float2half_rn(xs[i]);
        const uint32_t dst = base_u + (uint32_t)(buf*8192 + srow*64 + ssw*16);
        uint4 u; __half2 p;
        p = __halves2half2(hh[0], hh[1]); u.x = *(unsigned*)&p;
        p = __halves2half2(hh[2], hh[3]); u.y = *(unsigned*)&p;
        p = __halves2half2(hh[4], hh[5]); u.z = *(unsigned*)&p;
        p = __halves2half2(hh[6], hh[7]); u.w = *(unsigned*)&p;
        *(uint4*)__cvta_shared_to_generic(dst) = u;
        if (do_split) {
            __half ll[8];
            #pragma unroll
            for (int i = 0; i < 8; i++) ll[i] = __float2half_rn(xs[i] - __half2float(hh[i]));
            p = __halves2half2(ll[0], ll[1]); u.x = *(unsigned*)&p;
            p = __halves2half2(ll[2], ll[3]); u.y = *(unsigned*)&p;
            p = __halves2half2(ll[4], ll[5]); u.z = *(unsigned*)&p;
            p = __halves2half2(ll[6], ll[7]); u.w = *(unsigned*)&p;
            *(uint4*)__cvta_shared_to_generic(dst + 4096) = u;
        }
    };

    // ---- prime chunk 0 ----
    af[0] = *(const float4*)(Ag);     af[1] = *(const float4*)(Ag + 4);
    bf[0] = *(const float4*)(Wg);     bf[1] = *(const float4*)(Wg + 4);
    cvt_sts(af, sA_u, 0, split);
    cvt_sts(bf, sB_u, 0, split);
    __syncthreads();

    float d[4][4];
    #pragma unroll
    for (int i = 0; i < 4; i++) { d[i][0]=0.f; d[i][1]=0.f; d[i][2]=0.f; d[i][3]=0.f; }

    const int lrow = lane & 15;
    const int lks  = lane >> 4;
    const int arow = wr*16 + lrow;
    const uint32_t aswb = (uint32_t)((arow >> 1) & 3);

    for (int c = 0; c < 8; c++) {
        if (c + 1 < 8) {
            af[0] = *(const float4*)(Ag + (c+1)*32);
            af[1] = *(const float4*)(Ag + (c+1)*32 + 4);
            bf[0] = *(const float4*)(Wg + (c+1)*32);
            bf[1] = *(const float4*)(Wg + (c+1)*32 + 4);
        }
        const uint32_t bufo = (uint32_t)((c & 1) * 8192);

        #pragma unroll
        for (int ks = 0; ks < 2; ks++) {
            const uint32_t seg = (uint32_t)(ks*2 + lks);
            uint32_t ah[4], al[4];
            {
                uint32_t sw = seg ^ aswb;
                ldm_x4(sA_u + bufo + (uint32_t)arow*64 + sw*16, ah[0], ah[1], ah[2], ah[3]);
                if (split)
                    ldm_x4(sA_u + 4096 + bufo + (uint32_t)arow*64 + sw*16, al[0], al[1], al[2], al[3]);
            }
            #pragma unroll
            for (int bp = 0; bp < 2; bp++) {
                const int brow = wc*32 + bp*16 + lrow;
                const uint32_t sw = seg ^ (uint32_t)((brow >> 1) & 3);
                uint32_t bh0, bh1, bh2, bh3;
                ldm_x4(sB_u + bufo + (uint32_t)brow*64 + sw*16, bh0, bh1, bh2, bh3);
                mma16816(d[2*bp],   ah, bh0, bh2);
                mma16816(d[2*bp+1], ah, bh1, bh3);
                if (split) {
                    uint32_t bl0, bl1, bl2, bl3;
                    ldm_x4(sB_u + 4096 + bufo + (uint32_t)brow*64 + sw*16, bl0, bl1, bl2, bl3);
                    mma16816(d[2*bp],   ah, bl0, bl2);
                    mma16816(d[2*bp+1], ah, bl1, bl3);
                    mma16816(d[2*bp],   al, bh0, bh2);
                    mma16816(d[2*bp+1], al, bh1, bh3);
                }
            }
        }

        if (c + 1 < 8) {
            cvt_sts(af, sA_u, (c+1) & 1, split);
            cvt_sts(bf, sB_u, (c+1) & 1, split);
        }
        __syncthreads();
    }

    // ---- epilogue: bias + store (warp sub-tile 16x32) ----
    const int mrow = m0 + wr*16 + (lane >> 2);
    const int ncb  = n0 + wc*32 + 2*(lane & 3);
    #pragma unroll
    for (int t = 0; t < 4; t++) {         // t = 2*bp + h -> cols bp*16 + h*8
        const int n = ncb + t*8;
        float2 bb = *(const float2*)&bias[n];
        float v0 = d[t][0] + bb.x, v1 = d[t][1] + bb.y;
        float v2 = d[t][2] + bb.x, v3 = d[t][3] + bb.y;
        if (H) {
            __half2 p0 = __floats2half2_rn(v0, v1);
            __half2 p1 = __floats2half2_rn(v2, v3);
            *(unsigned*)&H[(size_t)mrow*N + n]     = *(unsigned*)&p0;
            *(unsigned*)&H[(size_t)(mrow+8)*N + n] = *(unsigned*)&p1;
        } else {
            *(float2*)&C[(size_t)mrow*N + n]     = make_float2(v0, v1);
            *(float2*)&C[(size_t)(mrow+8)*N + n] = make_float2(v2, v3);
        }
    }
}

// ---------------------------------------------------------------------------
// Fused additive-attention kernel, v12:
//  * score: CKK=32 (16 chunks), DOUBLE-BUFFERED K (2x4KB in union) ->
//    1 sync/chunk, STS off critical path. Hybrid MUFU/FMA tanh (f=3/8).
//  * AV: R13 staged (CKV=32 reg-prefetch, chunk 0 via cp.async over softmax).
// ---------------------------------------------------------------------------
#define SCT_PITCH 20
#define CKK 32
#define NCHK (SKL/CKK)    /* 16 */
#define CKV 32
#define NCHV (SKL/CKV)    /* 16 */
#define VF_PITCH 68
#define UNION_FLOATS 2176
#define ATTN_SMEM_FLOATS (SKL*SCT_PITCH + UNION_FLOATS + 512 + 32)

__global__ __launch_bounds__(256, 4) void attn_kernel(
    const float* __restrict__ vparam, float* __restrict__ attn_out)
{
    extern __shared__ float smem[];
    float*  scT = smem;                           // [512][20]
    float*  uni = scT + SKL*SCT_PITCH;            // union staging
    __half* qh  = (__half*)(uni + UNION_FLOATS);  // [16][64]
    __half* vh  = qh + 16*64;                     // [64]

    const int tid  = threadIdx.x;
    const int lane = tid & 31;
    const int warp = tid >> 5;
    const int b  = blockIdx.z;
    const int h  = blockIdx.y;
    const int q0t = blockIdx.x << 4;

    if (tid < 64) vh[tid] = __float2half(vparam[h*HDIM + tid]);
    {
        int row = tid >> 4;
        int seg = tid & 15;
        const uint2* src = (const uint2*)&g_Qh[((size_t)(b*SQL + q0t + row))*EMBED + h*HDIM + seg*4];
        *(uint2*)&qh[row*64 + seg*4] = *src;
    }

    const float scale = 0.125f;
    const int qa = warp*2;
    const int qb = qa + 1;

    // ===== score phase: 16 chunks of 32 k-rows, double-buffered K ==========
    {
        __half* kb0 = (__half*)uni;           // [32][64] swizzled
        __half* kb1 = kb0 + 2048;
        const int krow = tid >> 3;            // 0..31
        const int kseg = tid & 7;             // 16B segment of 128B row
        const int sseg = kseg ^ (krow & 7);   // swizzled segment
        const __half* Kg = &g_Kh[((size_t)(b*SKL))*EMBED + h*HDIM];

        uint4 kpre = *(const uint4*)(Kg + (size_t)krow*EMBED + kseg*8);
        *(uint4*)&kb0[krow*64 + sseg*8] = kpre;
        __syncthreads();

        for (int c = 0; c < NCHK; c++) {
            if (c + 1 < NCHK)
                kpre = *(const uint4*)(Kg + (size_t)((c+1)*CKK + krow)*EMBED + kseg*8);

            const uint4* qa4p = (const uint4*)&qh[qa*64];
            const uint4* qb4p = (const uint4*)&qh[qb*64];
            const uint4* vv4p = (const uint4*)vh;
            const __half* kr = ((c & 1) ? kb1 : kb0) + lane*64;
            const int sw = lane & 7;

            __half2 z = __float2half2_rn(0.f);
            __half2 accA0=z, accA1=z, accB0=z, accB1=z;

            #pragma unroll
            for (int db = 0; db < 8; db++) {
                const bool up = (db == 1) || (db == 4) || (db == 6);  // f=3/8 poly
                uint4 k4  = *(const uint4*)(kr + ((db ^ sw) * 8));
                uint4 qa4 = qa4p[db];
                uint4 qb4 = qb4p[db];
                uint4 vv4 = vv4p[db];

                __half2 k0=u2h(k4.x), k1=u2h(k4.y), k2=u2h(k4.z), k3=u2h(k4.w);
                __half2 qa0=u2h(qa4.x), qa1=u2h(qa4.y), qa2=u2h(qa4.z), qa3=u2h(qa4.w);
                __half2 qb0=u2h(qb4.x), qb1=u2h(qb4.y), qb2=u2h(qb4.z), qb3=u2h(qb4.w);
                __half2 v0=u2h(vv4.x), v1=u2h(vv4.y), v2=u2h(vv4.z), v3=u2h(vv4.w);

                accA0 = __hfma2(v0, tanh_mixed(__hadd2(qa0, k0), up), accA0);
                accB0 = __hfma2(v0, tanh_mixed(__hadd2(qb0, k0), up), accB0);
                accA1 = __hfma2(v1, tanh_mixed(__hadd2(qa1, k1), up), accA1);
                accB1 = __hfma2(v1, tanh_mixed(__hadd2(qb1, k1), up), accB1);
                accA0 = __hfma2(v2, tanh_mixed(__hadd2(qa2, k2), up), accA0);
                accB0 = __hfma2(v2, tanh_mixed(__hadd2(qb2, k2), up), accB0);
                accA1 = __hfma2(v3, tanh_mixed(__hadd2(qa3, k3), up), accA1);
                accB1 = __hfma2(v3, tanh_mixed(__hadd2(qb3, k3), up), accB1);
            }

            scT[(c*CKK + lane)*SCT_PITCH + qa] = (sumh2(accA0) + sumh2(accA1)) * scale;
            scT[(c*CKK + lane)*SCT_PITCH + qb] = (sumh2(accB0) + sumh2(accB1)) * scale;

            if (c + 1 < NCHK) {
                // other buffer: last read in chunk c-1 (barrier-protected) — safe
                __half* kw = ((c & 1) ? kb0 : kb1);
                *(uint4*)&kw[krow*64 + sseg*8] = kpre;
            }
            __syncthreads();
        }
    }

    // ---- prime V chunk 0 (32 rows) via cp.async, overlapping softmax ----
    {
        const int vrow  = tid >> 4;          // 0..15
        const int vseg4 = (tid & 15) << 2;   // 0,4,..,60
        const float* Vg = &g_V[((size_t)(b*SKL))*EMBED + h*HDIM];
        cp_async16_ca(&uni[vrow*VF_PITCH + vseg4],      Vg + (size_t)vrow*EMBED + vseg4);
        cp_async16_ca(&uni[(vrow+16)*VF_PITCH + vseg4], Vg + (size_t)(vrow+16)*EMBED + vseg4);
        cp_commit();
    }

    // ---------------- softmax (each warp: 2 rows of 512) ----------------
    #pragma unroll
    for (int qq = 0; qq < 2; qq++) {
        const int q = qa + qq;
        float x[16];
        #pragma unroll
        for (int j = 0; j < 16; j++) x[j] = scT[(lane + 32*j)*SCT_PITCH + q];
        float m = -1e30f;
        #pragma unroll
        for (int j = 0; j < 16; j++) m = fmaxf(m, x[j]);
        #pragma unroll
        for (int o = 16; o; o >>= 1) m = fmaxf(m, __shfl_xor_sync(0xffffffffu, m, o));
        float s = 0.f;
        #pragma unroll
        for (int j = 0; j < 16; j++) { x[j] = __expf(x[j] - m); s += x[j]; }
        #pragma unroll
        for (int o = 16; o; o >>= 1) s += __shfl_xor_sync(0xffffffffu, s, o);
        const float r = 1.0f / s;
        float* arow = attn_out + ((size_t)((b*HEADS + h)*SQL + q0t + q))*SKL;
        #pragma unroll
        for (int j = 0; j < 16; j++) {
            float p = x[j] * r;
            scT[(lane + 32*j)*SCT_PITCH + q] = p;
            arow[lane + 32*j] = p;
        }
    }

    // ========= AV phase: 16 chunks of 32 k-rows, reg-prefetch =========
    {
        float* kvf = uni;                    // [32][68]
        const int vrow  = tid >> 4;
        const int vseg4 = (tid & 15) << 2;
        const float* Vg = &g_V[((size_t)(b*SKL))*EMBED + h*HDIM];
        const int g  = lane >> 3;            // q-group: q = 4g..4g+3
        const int dl = warp*8 + (lane & 7);  // this thread's d

        cp_wait<0>();
        __syncthreads();                     // chunk 0 resident

        float4 vpre[2];
        float a0=0.f, a1=0.f, a2=0.f, a3=0.f;
        for (int c = 0; c < NCHV; c++) {
            if (c + 1 < NCHV) {
                #pragma unroll
                for (int it = 0; it < 2; it++)
                    vpre[it] = *(const float4*)(Vg + ((size_t)((c+1)*CKV + vrow + it*16))*EMBED + vseg4);
            }
            const float* pb  = &scT[(c*CKV)*SCT_PITCH + 4*g];
            const float* vbp = kvf + dl;
            #pragma unroll 8
            for (int kp = 0; kp < CKV; kp++) {
                float4 p = *(const float4*)(pb + kp*SCT_PITCH);
                float  v = vbp[kp*VF_PITCH];
                a0 += p.x*v; a1 += p.y*v; a2 += p.z*v; a3 += p.w*v;
            }
            __syncthreads();
            if (c + 1 < NCHV) {
                #pragma unroll
                for (int it = 0; it < 2; it++)
                    *(float4*)&kvf[(vrow + it*16)*VF_PITCH + vseg4] = vpre[it];
                __syncthreads();
            }
        }

        float* abase = &g_att[((size_t)(b*SQL + q0t + 4*g))*EMBED + h*HDIM + dl];
        abase[0]       = a0;
        abase[EMBED]   = a1;
        abase[2*EMBED] = a2;
        abase[3*EMBED] = a3;
    }
}

// ---------------------------------------------------------------------------
extern "C" void kernel_launch(void* const* d_in, const int* in_sizes, int n_in,
                              void* d_out, int out_size)
{
    (void)in_sizes; (void)n_in; (void)out_size;
    const float* query = (const float*)d_in[0];
    const float* key_  = (const float*)d_in[1];
    const float* value = (const float*)d_in[2];
    const float* Wq = (const float*)d_in[3];
    const float* bq = (const float*)d_in[4];
    const float* Wk = (const float*)d_in[5];
    const float* bk = (const float*)d_in[6];
    const float* Wv = (const float*)d_in[7];
    const float* bv = (const float*)d_in[8];
    const float* vp = (const float*)d_in[9];
    const float* Wo = (const float*)d_in[10];
    const float* bo = (const float*)d_in[11];

    float* out  = (float*)d_out;                 // [B, SQ, EMBED]
    float* attn = out + (size_t)MTOT * EMBED;    // [B, H, SQ, SK]

    __half *gQh, *gKh;
    float *gV, *gA;
    cudaGetSymbolAddress((void**)&gQh, g_Qh);
    cudaGetSymbolAddress((void**)&gKh, g_Kh);
    cudaGetSymbolAddress((void**)&gV,  g_V);
    cudaGetSymbolAddress((void**)&gA,  g_att);

    const int smem_bytes = ATTN_SMEM_FLOATS * (int)sizeof(float);
    cudaFuncSetAttribute(attn_kernel, cudaFuncAttributeMaxDynamicSharedMemorySize, smem_bytes);

    // Q,K: half out, single mma. V: f32 out, split mma.
    dim3 ggrid3(EMBED/64, MTOT/64, 3);   // (4, 32, 3)
    hgemm_bias3_kernel<<<ggrid3, 256>>>(query, key_, value,
                                        Wq, Wk, Wv,
                                        bq, bk, bv,
                                        nullptr, nullptr, gV,
                                        gQh, gKh, nullptr,
                                        0, 0, 1,
                                        MTOT, EMBED, EMBED);

    dim3 agrid(SQL/16, HEADS, BATCH);  // (32, 4, 4)
    attn_kernel<<<agrid, 256, smem_bytes>>>(vp, attn);

    // Output projection: f32 out, split mma.
    dim3 ggrid(EMBED/64, MTOT/64, 1);
    hgemm_bias3_kernel<<<ggrid, 256>>>(gA, gA, gA,
                                       Wo, Wo, Wo,
                                       bo, bo, bo,
                                       out, out, out,
                                       nullptr, nullptr, nullptr,
                                       1, 1, 1,
                                       MTOT, EMBED, EMBED);
}

// round 17
// speedup vs baseline: 1.2400x; 1.0017x over previous
#include <cuda_runtime.h>
#include <cuda_fp16.h>
#include <cstdint>

#define EMBED 256
#define HEADS 4
#define HDIM  64
#define BATCH 4
#define SQL   512
#define SKL   512
#define MTOT  (BATCH*SQL)   /* 2048 */

// Scratch (allocation-free rule: __device__ globals)
__device__ __half g_Qh[MTOT*EMBED];   // Q projection, half
__device__ __half g_Kh[MTOT*EMBED];   // K projection, half
__device__ __half g_Vh[MTOT*EMBED];   // V projection, half
__device__ float  g_att[MTOT*EMBED];  // attended, f32

__device__ __forceinline__ __half2 htanh2(__half2 x) {
    unsigned int xi = *reinterpret_cast<unsigned int*>(&x);
    unsigned int yi;
    asm("tanh.approx.f16x2 %0, %1;" : "=r"(yi) : "r"(xi));
    return *reinterpret_cast<__half2*>(&yi);
}

// FMA-pipe tanh: odd interpolant on |x|<=2.75 (clamped), t = xc * P(xc^2).
__device__ __forceinline__ __half2 poly_tanh2(__half2 x) {
    const __half2 lo = __float2half2_rn(-2.75f);
    const __half2 hi = __float2half2_rn( 2.75f);
    __half2 xc = __hmax2(lo, __hmin2(x, hi));
    __half2 u  = __hmul2(xc, xc);
    __half2 p  = __hfma2(u, __float2half2_rn(-6.3914e-05f), __float2half2_rn(1.60803e-03f));
    p = __hfma2(u, p, __float2half2_rn(-1.63146e-02f));
    p = __hfma2(u, p, __float2half2_rn( 8.88551e-02f));
    p = __hfma2(u, p, __float2half2_rn(-3.096166e-01f));
    p = __hfma2(u, p, __float2half2_rn( 9.975679e-01f));
    return __hmul2(xc, p);
}

__device__ __forceinline__ __half2 tanh_mixed(__half2 x, bool use_poly) {
    return use_poly ? poly_tanh2(x) : htanh2(x);
}

__device__ __forceinline__ float sumh2(__half2 h) {
    float2 f = __half22float2(h);
    return f.x + f.y;
}
__device__ __forceinline__ __half2 u2h(unsigned int u) {
    return *reinterpret_cast<__half2*>(&u);
}
__device__ __forceinline__ void cp_async16_ca(void* smem_dst, const void* gsrc) {
    unsigned int saddr = (unsigned int)__cvta_generic_to_shared(smem_dst);
    asm volatile("cp.async.ca.shared.global [%0], [%1], 16;\n" :: "r"(saddr), "l"(gsrc));
}
__device__ __forceinline__ void cp_commit() {
    asm volatile("cp.async.commit_group;\n");
}
template<int N>
__device__ __forceinline__ void cp_wait() {
    asm volatile("cp.async.wait_group %0;\n" :: "n"(N));
}

// ---- tensor-core helpers ----
__device__ __forceinline__ void ldm_x4(uint32_t addr, uint32_t &r0, uint32_t &r1,
                                       uint32_t &r2, uint32_t &r3) {
    asm volatile("ldmatrix.sync.aligned.m8n8.x4.shared.b16 {%0,%1,%2,%3}, [%4];"
                 : "=r"(r0), "=r"(r1), "=r"(r2), "=r"(r3) : "r"(addr));
}
__device__ __forceinline__ void mma16816(float* d, const uint32_t* a,
                                         uint32_t b0, uint32_t b1) {
    asm volatile("mma.sync.aligned.m16n8k16.row.col.f32.f16.f16.f32 "
                 "{%0,%1,%2,%3}, {%4,%5,%6,%7}, {%8,%9}, {%0,%1,%2,%3};"
                 : "+f"(d[0]), "+f"(d[1]), "+f"(d[2]), "+f"(d[3])
                 : "r"(a[0]), "r"(a[1]), "r"(a[2]), "r"(a[3]), "r"(b0), "r"(b1));
}

// ---------------------------------------------------------------------------
// HMMA GEMM v2: 256 threads (8 warps), 64x64 tile; warp (wr=w&3, wc=w>>2)
// owns a 16x32 sub-tile. k-chunk 32, double-buffered smem.
// split=0: single-half mma (Q/K/V). split=1: Markidis hi/lo, 3 mmas (out proj).
// ---------------------------------------------------------------------------
__global__ __launch_bounds__(256) void hgemm_bias3_kernel(
    const float* __restrict__ A0, const float* __restrict__ A1, const float* __restrict__ A2,
    const float* __restrict__ W0, const float* __restrict__ W1, const float* __restrict__ W2,
    const float* __restrict__ b0, const float* __restrict__ b1, const float* __restrict__ b2,
    float* __restrict__ C0, float* __restrict__ C1, float* __restrict__ C2,
    __half* __restrict__ H0, __half* __restrict__ H1, __half* __restrict__ H2,
    int s0, int s1, int s2,
    int M, int N, int K)
{
    const float* A; const float* W; const float* bias; float* C; __half* H; int split;
    if (blockIdx.z == 0)      { A = A0; W = W0; bias = b0; C = C0; H = H0; split = s0; }
    else if (blockIdx.z == 1) { A = A1; W = W1; bias = b1; C = C1; H = H1; split = s1; }
    else                      { A = A2; W = W2; bias = b2; C = C2; H = H2; split = s2; }

    __shared__ __half sA[2][2][64][32];   // [buf][hi/lo][row][col]
    __shared__ __half sB[2][2][64][32];

    const int tid  = threadIdx.x;
    const int lane = tid & 31;
    const int w    = tid >> 5;           // 0..7
    const int wr   = w & 3;              // m sub-tile
    const int wc   = w >> 2;             // n half (0/1)
    const int n0   = blockIdx.x * 64;
    const int m0   = blockIdx.y * 64;

    const uint32_t sA_u = (uint32_t)__cvta_generic_to_shared(&sA[0][0][0][0]);
    const uint32_t sB_u = (uint32_t)__cvta_generic_to_shared(&sB[0][0][0][0]);

    const int srow = tid >> 2;
    const int hs   = tid & 3;
    const int ssw  = hs ^ ((srow >> 1) & 3);
    const float* Ag = A + (size_t)(m0 + srow) * K + hs * 8;
    const float* Wg = W + (size_t)(n0 + srow) * K + hs * 8;

    float4 af[2], bf[2];

    auto cvt_sts = [&](const float4* f, uint32_t base_u, int buf, int do_split) {
        const float* xs = (const float*)f;
        __half hh[8];
        #pragma unroll
        for (int i = 0; i < 8; i++) hh[i] = __float2half_rn(xs[i]);
        const uint32_t dst = base_u + (uint32_t)(buf*8192 + srow*64 + ssw*16);
        uint4 u; __half2 p;
        p = __halves2half2(hh[0], hh[1]); u.x = *(unsigned*)&p;
        p = __halves2half2(hh[2], hh[3]); u.y = *(unsigned*)&p;
        p = __halves2half2(hh[4], hh[5]); u.z = *(unsigned*)&p;
        p = __halves2half2(hh[6], hh[7]); u.w = *(unsigned*)&p;
        *(uint4*)__cvta_shared_to_generic(dst) = u;
        if (do_split) {
            __half ll[8];
            #pragma unroll
            for (int i = 0; i < 8; i++) ll[i] = __float2half_rn(xs[i] - __half2float(hh[i]));
            p = __halves2half2(ll[0], ll[1]); u.x = *(unsigned*)&p;
            p = __halves2half2(ll[2], ll[3]); u.y = *(unsigned*)&p;
            p = __halves2half2(ll[4], ll[5]); u.z = *(unsigned*)&p;
            p = __halves2half2(ll[6], ll[7]); u.w = *(unsigned*)&p;
            *(uint4*)__cvta_shared_to_generic(dst + 4096) = u;
        }
    };

    // ---- prime chunk 0 ----
    af[0] = *(const float4*)(Ag);     af[1] = *(const float4*)(Ag + 4);
    bf[0] = *(const float4*)(Wg);     bf[1] = *(const float4*)(Wg + 4);
    cvt_sts(af, sA_u, 0, split);
    cvt_sts(bf, sB_u, 0, split);
    __syncthreads();

    float d[4][4];
    #pragma unroll
    for (int i = 0; i < 4; i++) { d[i][0]=0.f; d[i][1]=0.f; d[i][2]=0.f; d[i][3]=0.f; }

    const int lrow = lane & 15;
    const int lks  = lane >> 4;
    const int arow = wr*16 + lrow;
    const uint32_t aswb = (uint32_t)((arow >> 1) & 3);

    for (int c = 0; c < 8; c++) {
        if (c + 1 < 8) {
            af[0] = *(const float4*)(Ag + (c+1)*32);
            af[1] = *(const float4*)(Ag + (c+1)*32 + 4);
            bf[0] = *(const float4*)(Wg + (c+1)*32);
            bf[1] = *(const float4*)(Wg + (c+1)*32 + 4);
        }
        const uint32_t bufo = (uint32_t)((c & 1) * 8192);

        #pragma unroll
        for (int ks = 0; ks < 2; ks++) {
            const uint32_t seg = (uint32_t)(ks*2 + lks);
            uint32_t ah[4], al[4];
            {
                uint32_t sw = seg ^ aswb;
                ldm_x4(sA_u + bufo + (uint32_t)arow*64 + sw*16, ah[0], ah[1], ah[2], ah[3]);
                if (split)
                    ldm_x4(sA_u + 4096 + bufo + (uint32_t)arow*64 + sw*16, al[0], al[1], al[2], al[3]);
            }
            #pragma unroll
            for (int bp = 0; bp < 2; bp++) {
                const int brow = wc*32 + bp*16 + lrow;
                const uint32_t sw = seg ^ (uint32_t)((brow >> 1) & 3);
                uint32_t bh0, bh1, bh2, bh3;
                ldm_x4(sB_u + bufo + (uint32_t)brow*64 + sw*16, bh0, bh1, bh2, bh3);
                mma16816(d[2*bp],   ah, bh0, bh2);
                mma16816(d[2*bp+1], ah, bh1, bh3);
                if (split) {
                    uint32_t bl0, bl1, bl2, bl3;
                    ldm_x4(sB_u + 4096 + bufo + (uint32_t)brow*64 + sw*16, bl0, bl1, bl2, bl3);
                    mma16816(d[2*bp],   ah, bl0, bl2);
                    mma16816(d[2*bp+1], ah, bl1, bl3);
                    mma16816(d[2*bp],   al, bh0, bh2);
                    mma16816(d[2*bp+1], al, bh1, bh3);
                }
            }
        }

        if (c + 1 < 8) {
            cvt_sts(af, sA_u, (c+1) & 1, split);
            cvt_sts(bf, sB_u, (c+1) & 1, split);
        }
        __syncthreads();
    }

    // ---- epilogue: bias + store (warp sub-tile 16x32) ----
    const int mrow = m0 + wr*16 + (lane >> 2);
    const int ncb  = n0 + wc*32 + 2*(lane & 3);
    #pragma unroll
    for (int t = 0; t < 4; t++) {
        const int n = ncb + t*8;
        float2 bb = *(const float2*)&bias[n];
        float v0 = d[t][0] + bb.x, v1 = d[t][1] + bb.y;
        float v2 = d[t][2] + bb.x, v3 = d[t][3] + bb.y;
        if (H) {
            __half2 p0 = __floats2half2_rn(v0, v1);
            __half2 p1 = __floats2half2_rn(v2, v3);
            *(unsigned*)&H[(size_t)mrow*N + n]     = *(unsigned*)&p0;
            *(unsigned*)&H[(size_t)(mrow+8)*N + n] = *(unsigned*)&p1;
        } else {
            *(float2*)&C[(size_t)mrow*N + n]     = make_float2(v0, v1);
            *(float2*)&C[(size_t)(mrow+8)*N + n] = make_float2(v2, v3);
        }
    }
}

// ---------------------------------------------------------------------------
// Fused additive-attention kernel, v13:
//  * score: CKK=32 (16 chunks), double-buffered K, 1 sync/chunk, hybrid tanh.
//  * AV: half V, double-buffered (2x4KB, no swizzle needed), reg-prefetch,
//    1 sync/chunk (17 AV syncs vs 31); chunk 0 via cp.async over softmax.
// Smem floats: scT 10240 + union 2176 + qh 512 + vh 32 = 51840B -> 4 blk/SM.
// ---------------------------------------------------------------------------
#define SCT_PITCH 20
#define CKK 32
#define NCHK (SKL/CKK)    /* 16 */
#define CKV 32
#define NCHV (SKL/CKV)    /* 16 */
#define UNION_FLOATS 2176
#define ATTN_SMEM_FLOATS (SKL*SCT_PITCH + UNION_FLOATS + 512 + 32)

__global__ __launch_bounds__(256, 4) void attn_kernel(
    const float* __restrict__ vparam, float* __restrict__ attn_out)
{
    extern __shared__ float smem[];
    float*  scT = smem;                           // [512][20]
    float*  uni = scT + SKL*SCT_PITCH;            // union staging
    __half* qh  = (__half*)(uni + UNION_FLOATS);  // [16][64]
    __half* vh  = qh + 16*64;                     // [64]

    const int tid  = threadIdx.x;
    const int lane = tid & 31;
    const int warp = tid >> 5;
    const int b  = blockIdx.z;
    const int h  = blockIdx.y;
    const int q0t = blockIdx.x << 4;

    if (tid < 64) vh[tid] = __float2half(vparam[h*HDIM + tid]);
    {
        int row = tid >> 4;
        int seg = tid & 15;
        const uint2* src = (const uint2*)&g_Qh[((size_t)(b*SQL + q0t + row))*EMBED + h*HDIM + seg*4];
        *(uint2*)&qh[row*64 + seg*4] = *src;
    }

    const float scale = 0.125f;
    const int qa = warp*2;
    const int qb = qa + 1;

    // ===== score phase: 16 chunks of 32 k-rows, double-buffered K ==========
    {
        __half* kb0 = (__half*)uni;           // [32][64] swizzled
        __half* kb1 = kb0 + 2048;
        const int krow = tid >> 3;            // 0..31
        const int kseg = tid & 7;             // 16B segment of 128B row
        const int sseg = kseg ^ (krow & 7);   // swizzled segment
        const __half* Kg = &g_Kh[((size_t)(b*SKL))*EMBED + h*HDIM];

        uint4 kpre = *(const uint4*)(Kg + (size_t)krow*EMBED + kseg*8);
        *(uint4*)&kb0[krow*64 + sseg*8] = kpre;
        __syncthreads();

        for (int c = 0; c < NCHK; c++) {
            if (c + 1 < NCHK)
                kpre = *(const uint4*)(Kg + (size_t)((c+1)*CKK + krow)*EMBED + kseg*8);

            const uint4* qa4p = (const uint4*)&qh[qa*64];
            const uint4* qb4p = (const uint4*)&qh[qb*64];
            const uint4* vv4p = (const uint4*)vh;
            const __half* kr = ((c & 1) ? kb1 : kb0) + lane*64;
            const int sw = lane & 7;

            __half2 z = __float2half2_rn(0.f);
            __half2 accA0=z, accA1=z, accB0=z, accB1=z;

            #pragma unroll
            for (int db = 0; db < 8; db++) {
                const bool up = (db == 1) || (db == 4) || (db == 6);  // f=3/8 poly
                uint4 k4  = *(const uint4*)(kr + ((db ^ sw) * 8));
                uint4 qa4 = qa4p[db];
                uint4 qb4 = qb4p[db];
                uint4 vv4 = vv4p[db];

                __half2 k0=u2h(k4.x), k1=u2h(k4.y), k2=u2h(k4.z), k3=u2h(k4.w);
                __half2 qa0=u2h(qa4.x), qa1=u2h(qa4.y), qa2=u2h(qa4.z), qa3=u2h(qa4.w);
                __half2 qb0=u2h(qb4.x), qb1=u2h(qb4.y), qb2=u2h(qb4.z), qb3=u2h(qb4.w);
                __half2 v0=u2h(vv4.x), v1=u2h(vv4.y), v2=u2h(vv4.z), v3=u2h(vv4.w);

                accA0 = __hfma2(v0, tanh_mixed(__hadd2(qa0, k0), up), accA0);
                accB0 = __hfma2(v0, tanh_mixed(__hadd2(qb0, k0), up), accB0);
                accA1 = __hfma2(v1, tanh_mixed(__hadd2(qa1, k1), up), accA1);
                accB1 = __hfma2(v1, tanh_mixed(__hadd2(qb1, k1), up), accB1);
                accA0 = __hfma2(v2, tanh_mixed(__hadd2(qa2, k2), up), accA0);
                accB0 = __hfma2(v2, tanh_mixed(__hadd2(qb2, k2), up), accB0);
                accA1 = __hfma2(v3, tanh_mixed(__hadd2(qa3, k3), up), accA1);
                accB1 = __hfma2(v3, tanh_mixed(__hadd2(qb3, k3), up), accB1);
            }

            scT[(c*CKK + lane)*SCT_PITCH + qa] = (sumh2(accA0) + sumh2(accA1)) * scale;
            scT[(c*CKK + lane)*SCT_PITCH + qb] = (sumh2(accB0) + sumh2(accB1)) * scale;

            if (c + 1 < NCHK) {
                __half* kw = ((c & 1) ? kb0 : kb1);
                *(uint4*)&kw[krow*64 + sseg*8] = kpre;
            }
            __syncthreads();
        }
    }

    // ---- prime V chunk 0 (32 rows, half) via cp.async, overlapping softmax --
    {
        const int krow = tid >> 3;
        const int kseg = tid & 7;
        const __half* Vg = &g_Vh[((size_t)(b*SKL))*EMBED + h*HDIM];
        __half* vb0 = (__half*)uni;
        cp_async16_ca(&vb0[krow*64 + kseg*8], Vg + (size_t)krow*EMBED + kseg*8);
        cp_commit();
    }

    // ---------------- softmax (each warp: 2 rows of 512) ----------------
    #pragma unroll
    for (int qq = 0; qq < 2; qq++) {
        const int q = qa + qq;
        float x[16];
        #pragma unroll
        for (int j = 0; j < 16; j++) x[j] = scT[(lane + 32*j)*SCT_PITCH + q];
        float m = -1e30f;
        #pragma unroll
        for (int j = 0; j < 16; j++) m = fmaxf(m, x[j]);
        #pragma unroll
        for (int o = 16; o; o >>= 1) m = fmaxf(m, __shfl_xor_sync(0xffffffffu, m, o));
        float s = 0.f;
        #pragma unroll
        for (int j = 0; j < 16; j++) { x[j] = __expf(x[j] - m); s += x[j]; }
        #pragma unroll
        for (int o = 16; o; o >>= 1) s += __shfl_xor_sync(0xffffffffu, s, o);
        const float r = 1.0f / s;
        float* arow = attn_out + ((size_t)((b*HEADS + h)*SQL + q0t + q))*SKL;
        #pragma unroll
        for (int j = 0; j < 16; j++) {
            float p = x[j] * r;
            scT[(lane + 32*j)*SCT_PITCH + q] = p;
            arow[lane + 32*j] = p;
        }
    }

    // ====== AV phase: 16 chunks of 32 k-rows, half V, double-buffered =======
    {
        __half* vb0 = (__half*)uni;           // [32][64] halves, linear
        __half* vb1 = vb0 + 2048;
        const int krow = tid >> 3;
        const int kseg = tid & 7;
        const __half* Vg = &g_Vh[((size_t)(b*SKL))*EMBED + h*HDIM];
        const int g  = lane >> 3;             // q-group: q = 4g..4g+3
        const int dl = warp*8 + (lane & 7);   // this thread's d

        cp_wait<0>();
        __syncthreads();                      // chunk 0 resident

        uint4 vpre;
        float a0=0.f, a1=0.f, a2=0.f, a3=0.f;
        for (int c = 0; c < NCHV; c++) {
            if (c + 1 < NCHV)
                vpre = *(const uint4*)(Vg + (size_t)((c+1)*CKV + krow)*EMBED + kseg*8);

            const float*  pb  = &scT[(c*CKV)*SCT_PITCH + 4*g];
            const __half* vbp = ((c & 1) ? vb1 : vb0) + dl;
            #pragma unroll 8
            for (int kp = 0; kp < CKV; kp++) {
                float4 p = *(const float4*)(pb + kp*SCT_PITCH);
                float  v = __half2float(vbp[kp*64]);
                a0 += p.x*v; a1 += p.y*v; a2 += p.z*v; a3 += p.w*v;
            }

            if (c + 1 < NCHV) {
                __half* vw = ((c & 1) ? vb0 : vb1);
                *(uint4*)&vw[krow*64 + kseg*8] = vpre;
            }
            __syncthreads();
        }

        float* abase = &g_att[((size_t)(b*SQL + q0t + 4*g))*EMBED + h*HDIM + dl];
        abase[0]       = a0;
        abase[EMBED]   = a1;
        abase[2*EMBED] = a2;
        abase[3*EMBED] = a3;
    }
}

// ---------------------------------------------------------------------------
extern "C" void kernel_launch(void* const* d_in, const int* in_sizes, int n_in,
                              void* d_out, int out_size)
{
    (void)in_sizes; (void)n_in; (void)out_size;
    const float* query = (const float*)d_in[0];
    const float* key_  = (const float*)d_in[1];
    const float* value = (const float*)d_in[2];
    const float* Wq = (const float*)d_in[3];
    const float* bq = (const float*)d_in[4];
    const float* Wk = (const float*)d_in[5];
    const float* bk = (const float*)d_in[6];
    const float* Wv = (const float*)d_in[7];
    const float* bv = (const float*)d_in[8];
    const float* vp = (const float*)d_in[9];
    const float* Wo = (const float*)d_in[10];
    const float* bo = (const float*)d_in[11];

    float* out  = (float*)d_out;                 // [B, SQ, EMBED]
    float* attn = out + (size_t)MTOT * EMBED;    // [B, H, SQ, SK]

    __half *gQh, *gKh, *gVh;
    float *gA;
    cudaGetSymbolAddress((void**)&gQh, g_Qh);
    cudaGetSymbolAddress((void**)&gKh, g_Kh);
    cudaGetSymbolAddress((void**)&gVh, g_Vh);
    cudaGetSymbolAddress((void**)&gA,  g_att);

    const int smem_bytes = ATTN_SMEM_FLOATS * (int)sizeof(float);
    cudaFuncSetAttribute(attn_kernel, cudaFuncAttributeMaxDynamicSharedMemorySize, smem_bytes);

    // Q,K,V all half out, single mma.
    dim3 ggrid3(EMBED/64, MTOT/64, 3);   // (4, 32, 3)
    hgemm_bias3_kernel<<<ggrid3, 256>>>(query, key_, value,
                                        Wq, Wk, Wv,
                                        bq, bk, bv,
                                        nullptr, nullptr, nullptr,
                                        gQh, gKh, gVh,
                                        0, 0, 0,
                                        MTOT, EMBED, EMBED);

    dim3 agrid(SQL/16, HEADS, BATCH);  // (32, 4, 4)
    attn_kernel<<<agrid, 256, smem_bytes>>>(vp, attn);

    // Output projection: f32 out, split mma (accuracy).
    dim3 ggrid(EMBED/64, MTOT/64, 1);
    hgemm_bias3_kernel<<<ggrid, 256>>>(gA, gA, gA,
                                       Wo, Wo, Wo,
                                       bo, bo, bo,
                                       out, out, out,
                                       nullptr, nullptr, nullptr,
                                       1, 1, 1,
                                       MTOT, EMBED, EMBED);
}